// round 9
// baseline (speedup 1.0000x reference)
#include <cuda_runtime.h>
#include <cuda_fp16.h>
#include <math.h>
#include <stdint.h>

#define E_N 64
#define H_N 512
#define F_N 2048
#define HB_STRIDE 3072   // padded token columns across all experts

// Intermediate activations, [f][padded token], zero-initialized at load.
__device__ float g_hbufT[(size_t)F_N * HB_STRIDE];  // 24 MB

__device__ __forceinline__ float gelu_exact(float v) {
    return 0.5f * v * (1.0f + erff(v * 0.70710678118654752f));
}
// Pack two fp32 into half2: lo = a, hi = b.
__device__ __forceinline__ uint32_t pack2(float a, float b) {
    uint32_t u;
    asm("cvt.rn.f16x2.f32 %0, %1, %2;" : "=r"(u) : "f"(b), "f"(a));
    return u;
}
__device__ __forceinline__ void mma16(float c[4], uint32_t a0, uint32_t a1,
                                      uint32_t a2, uint32_t a3,
                                      uint32_t b0, uint32_t b1) {
    asm volatile(
        "mma.sync.aligned.m16n8k16.row.col.f32.f16.f16.f32 "
        "{%0,%1,%2,%3},{%4,%5,%6,%7},{%8,%9},{%0,%1,%2,%3};"
        : "+f"(c[0]), "+f"(c[1]), "+f"(c[2]), "+f"(c[3])
        : "r"(a0), "r"(a1), "r"(a2), "r"(a3), "r"(b0), "r"(b1));
}
__device__ __forceinline__ void cp16(uint32_t dst, const void* src) {
    asm volatile("cp.async.cg.shared.global [%0], [%1], 16;"
                 :: "r"(dst), "l"(src) : "memory");
}
__device__ __forceinline__ void cp_commit() {
    asm volatile("cp.async.commit_group;" ::: "memory");
}
template <int N>
__device__ __forceinline__ void cp_wait() {
    asm volatile("cp.async.wait_group %0;" :: "n"(N) : "memory");
}

// ---------------------------------------------------------------------------
// 256 threads, BM=128 (one 16-row m-block per warp), BN=48, BK=32.
// A tiles (weights): fp32 in smem via cp.async, 4 slots of 16 KB:
//   PHASE 1 [m 128][k 32]: byte(m,k) = m*128 + ((k>>2)^(m&7))*16 + (k&3)*4
//   PHASE 2 [k 32][h 128]: byte(k,h) = k*512 + ((h>>2)^(k&7))*16 + (h&3)*4
// B tiles: fp16 fragment-pair layout, 2 buffers:
//   u32 (n, kpair p) at ((n>>3)*2 + (p>>3))*66 + (n&7)*8 + (p&3)*2 + ((p&7)>>2)
// Schedule (one __syncthreads per chunk):
//   iter c: wait_group(2); bar; stsB(c+1); ldB(c+3); cpA(c+3); commit; MMA(c)
// ---------------------------------------------------------------------------
#define A_SLOT_B 16384
#define BSZ_U32 (6 * 2 * 66)
#define SMEM_BYTES (4 * A_SLOT_B + 2 * BSZ_U32 * 4)   // 71872 -> 3 CTAs/SM

template <int PHASE>
__global__ void __launch_bounds__(256)
mlp_kernel(const float* __restrict__ x, const float* __restrict__ wgt,
           const int* __restrict__ counts, float* __restrict__ outp) {
    constexpr int KTOT = (PHASE == 1) ? H_N : F_N;
    constexpr int NCH  = KTOT / 32;

    extern __shared__ __align__(16) uint8_t smem_raw[];
    uint8_t*  Ab  = smem_raw;                               // 4 fp32 A slots
    uint32_t* Bh  = (uint32_t*)(smem_raw + 4 * A_SLOT_B);   // 2 fp16 B bufs
    const uint32_t aAddr = (uint32_t)__cvta_generic_to_shared(Ab);

    const int tid = threadIdx.x;
    const int w = tid >> 5, lane = tid & 31;
    const int g = lane >> 2, tg = lane & 3;
    const int e = blockIdx.y;
    const int mbase = blockIdx.x * 128;

    // ---- in-kernel scan of tokens_per_expert (warp 0) ----
    __shared__ int s_sc[3];
    if (tid < 32) {
        const unsigned FULL = 0xffffffffu;
        int c0 = counts[lane], c1 = counts[lane + 32];
        int p0 = (c0 + 15) & ~15, p1 = (c1 + 15) & ~15;
        int i0 = c0, i1 = c1, q0 = p0, q1 = p1;
        #pragma unroll
        for (int d = 1; d < 32; d <<= 1) {
            int t;
            t = __shfl_up_sync(FULL, i0, d); if (lane >= d) i0 += t;
            t = __shfl_up_sync(FULL, i1, d); if (lane >= d) i1 += t;
            t = __shfl_up_sync(FULL, q0, d); if (lane >= d) q0 += t;
            t = __shfl_up_sync(FULL, q1, d); if (lane >= d) q1 += t;
        }
        int tot0  = __shfl_sync(FULL, i0, 31);
        int ptot0 = __shfl_sync(FULL, q0, 31);
        int el = e & 31, ex, cc, pex;
        if (e < 32) {
            ex  = __shfl_sync(FULL, i0, el) - __shfl_sync(FULL, c0, el);
            cc  = __shfl_sync(FULL, c0, el);
            pex = __shfl_sync(FULL, q0, el) - __shfl_sync(FULL, p0, el);
        } else {
            ex  = tot0 + __shfl_sync(FULL, i1, el) - __shfl_sync(FULL, c1, el);
            cc  = __shfl_sync(FULL, c1, el);
            pex = ptot0 + __shfl_sync(FULL, q1, el) - __shfl_sync(FULL, p1, el);
        }
        if (lane == 0) { s_sc[0] = ex; s_sc[1] = cc; s_sc[2] = pex; }
    }
    __syncthreads();
    const int toff = s_sc[0], cnt = s_sc[1], poff = s_sc[2];
    const float* we = wgt + (size_t)e * F_N * H_N;

    float4 rB[2][2];

    for (int tbase = 0; tbase < cnt; tbase += 48) {
        const int nlim = (cnt - tbase < 48) ? (cnt - tbase) : 48;
        const int nbl  = (nlim + 7) >> 3;

        // ---- A producer: cp.async chunk c -> slot (4 x 16B per thread) ----
        auto cpA = [&](int slot, int c) {
            const int k0 = c * 32;
            const uint32_t sb = aAddr + slot * A_SLOT_B;
            #pragma unroll
            for (int i = 0; i < 4; ++i) {
                int q = tid + i * 256;
                if (PHASE == 1) {
                    int m = q >> 3, u = q & 7;       // u: 16B chunk along k
                    cp16(sb + m * 128 + ((u ^ (m & 7)) << 4),
                         we + (size_t)(mbase + m) * H_N + k0 + u * 4);
                } else {
                    int k = q >> 5, u = q & 31;      // u: 16B chunk along h
                    cp16(sb + k * 512 + ((u ^ (k & 7)) << 4),
                         we + (size_t)(k0 + k) * H_N + mbase + u * 4);
                }
            }
        };
        // ---- B producer: gmem -> regs ----
        auto ldB = [&](int set, int c) {
            const int k0 = c * 32;
            if (PHASE == 1) {
                #pragma unroll
                for (int i = 0; i < 2; ++i) {      // 48 t x 8 k4 = 384 slots
                    int q = tid + i * 256;
                    if (q < 384) {
                        int t = q >> 3, k4 = q & 7;
                        if (tbase + t < cnt)
                            rB[set][i] = *(const float4*)&x[(size_t)(toff + tbase + t) * H_N + k0 + k4 * 4];
                        else
                            rB[set][i] = make_float4(0.f, 0.f, 0.f, 0.f);
                    }
                }
            } else {
                int q = tid;                        // 12 n4 x 16 kp = 192 slots
                if (q < 192) {
                    int n4 = q % 12, kp = q / 12;
                    const float* p0 = &g_hbufT[(size_t)(k0 + 2 * kp) * HB_STRIDE +
                                               poff + tbase + n4 * 4];
                    rB[set][0] = *(const float4*)p0;
                    rB[set][1] = *(const float4*)(p0 + HB_STRIDE);
                }
            }
        };
        auto bidx = [](int n, int p) {
            int pb = p & 7;
            return ((n >> 3) * 2 + (p >> 3)) * 66 + (n & 7) * 8 + (pb & 3) * 2 + (pb >> 2);
        };
        auto stsB = [&](int buf, int set) {
            uint32_t* Bs = Bh + buf * BSZ_U32;
            if (PHASE == 1) {
                #pragma unroll
                for (int i = 0; i < 2; ++i) {
                    int q = tid + i * 256;
                    if (q < 384) {
                        int t = q >> 3, k4 = q & 7;
                        Bs[bidx(t, 2 * k4)]     = pack2(rB[set][i].x, rB[set][i].y);
                        Bs[bidx(t, 2 * k4 + 1)] = pack2(rB[set][i].z, rB[set][i].w);
                    }
                }
            } else {
                int q = tid;
                if (q < 192) {
                    int n4 = q % 12, kp = q / 12;
                    const float* a = (const float*)&rB[set][0];
                    const float* b = (const float*)&rB[set][1];
                    #pragma unroll
                    for (int j = 0; j < 4; ++j)
                        Bs[bidx(n4 * 4 + j, kp)] = pack2(a[j], b[j]);
                }
            }
        };

        float acc[6][4];
        #pragma unroll
        for (int nb = 0; nb < 6; ++nb)
            #pragma unroll
            for (int r = 0; r < 4; ++r) acc[nb][r] = 0.f;

        // -------- prologue --------
        ldB(0, 0); ldB(1, 1);
        stsB(0, 0);
        ldB(0, 2);
        cpA(0, 0); cp_commit();
        cpA(1, 1); cp_commit();
        cpA(2, 2); cp_commit();
        __syncthreads();

        // -------- mainloop: one barrier per chunk --------
        for (int c = 0; c < NCH; ++c) {
            cp_wait<2>();
            __syncthreads();
            if (c + 1 < NCH) stsB((c + 1) & 1, (c + 1) & 1);
            if (c + 3 < NCH) { ldB((c + 3) & 1, c + 3); cpA((c + 3) & 3, c + 3); }
            cp_commit();

            const uint8_t*  As = Ab + (c & 3) * A_SLOT_B;
            const uint32_t* Bs = Bh + (c & 1) * BSZ_U32;
            const int m0 = w * 16 + g;
            #pragma unroll
            for (int kb = 0; kb < 2; ++kb) {
                const int k = 2 * tg + 16 * kb;
                uint32_t a[4];
                if (PHASE == 1) {
                    auto ld2 = [&](int m, int kk) -> float2 {
                        int off = m * 128 + (((kk >> 2) ^ (m & 7)) << 4) + ((kk & 3) << 2);
                        return *(const float2*)(As + off);
                    };
                    float2 v00 = ld2(m0, k),     v10 = ld2(m0 + 8, k);
                    float2 v01 = ld2(m0, k + 8), v11 = ld2(m0 + 8, k + 8);
                    a[0] = pack2(v00.x, v00.y);
                    a[1] = pack2(v10.x, v10.y);
                    a[2] = pack2(v01.x, v01.y);
                    a[3] = pack2(v11.x, v11.y);
                } else {
                    auto ld1 = [&](int kk, int h) -> float {
                        int off = kk * 512 + (((h >> 2) ^ (kk & 7)) << 4) + ((h & 3) << 2);
                        return *(const float*)(As + off);
                    };
                    a[0] = pack2(ld1(k, m0),     ld1(k + 1, m0));
                    a[1] = pack2(ld1(k, m0 + 8), ld1(k + 1, m0 + 8));
                    a[2] = pack2(ld1(k + 8, m0),     ld1(k + 9, m0));
                    a[3] = pack2(ld1(k + 8, m0 + 8), ld1(k + 9, m0 + 8));
                }
                #pragma unroll
                for (int nb = 0; nb < 6; ++nb) {
                    if (nb < nbl) {
                        const uint32_t* bb = &Bs[(nb * 2 + kb) * 66];
                        uint2 pb = *(const uint2*)&bb[2 * lane];
                        mma16(acc[nb], a[0], a[1], a[2], a[3], pb.x, pb.y);
                    }
                }
            }
            __syncthreads();
        }
        cp_wait<0>();

        // -------- epilogue --------
        {
            const int r0 = mbase + w * 16 + g;
            const int r1 = r0 + 8;
            #pragma unroll
            for (int nb = 0; nb < 6; ++nb) {
                const int n0 = nb * 8 + tg * 2;
                const float* c4 = acc[nb];
                if (PHASE == 1) {
                    size_t b0 = (size_t)r0 * HB_STRIDE + poff + tbase + n0;
                    size_t b1 = (size_t)r1 * HB_STRIDE + poff + tbase + n0;
                    if (n0 + 1 < nlim) {
                        *(float2*)&g_hbufT[b0] = make_float2(gelu_exact(c4[0]), gelu_exact(c4[1]));
                        *(float2*)&g_hbufT[b1] = make_float2(gelu_exact(c4[2]), gelu_exact(c4[3]));
                    } else if (n0 < nlim) {
                        g_hbufT[b0] = gelu_exact(c4[0]);
                        g_hbufT[b1] = gelu_exact(c4[2]);
                    }
                } else {
                    const int t0 = toff + tbase + n0;
                    if (n0 < nlim) {
                        outp[(size_t)t0 * H_N + r0] = c4[0];
                        outp[(size_t)t0 * H_N + r1] = c4[2];
                    }
                    if (n0 + 1 < nlim) {
                        outp[(size_t)(t0 + 1) * H_N + r0] = c4[1];
                        outp[(size_t)(t0 + 1) * H_N + r1] = c4[3];
                    }
                }
            }
        }
        __syncthreads();  // smem reuse across token tiles
    }
}

// ---------------------------------------------------------------------------
// Inputs: d_in[0]=x [T,H] f32, d_in[1]=w1 [E,F,H] f32, d_in[2]=w2 [E,F,H] f32,
//         d_in[3]=tokens_per_expert [E] i32.  d_out=[T,H] f32.
// ---------------------------------------------------------------------------
extern "C" void kernel_launch(void* const* d_in, const int* in_sizes, int n_in,
                              void* d_out, int out_size) {
    const float* x      = (const float*)d_in[0];
    const float* w1     = (const float*)d_in[1];
    const float* w2     = (const float*)d_in[2];
    const int*   counts = (const int*)d_in[3];
    float* out = (float*)d_out;

    cudaFuncSetAttribute(mlp_kernel<1>, cudaFuncAttributeMaxDynamicSharedMemorySize, SMEM_BYTES);
    cudaFuncSetAttribute(mlp_kernel<2>, cudaFuncAttributeMaxDynamicSharedMemorySize, SMEM_BYTES);

    mlp_kernel<1><<<dim3(F_N / 128, E_N), 256, SMEM_BYTES>>>(x, w1, counts, nullptr);
    mlp_kernel<2><<<dim3(H_N / 128, E_N), 256, SMEM_BYTES>>>(x, w2, counts, out);
}

// round 12
// speedup vs baseline: 1.0490x; 1.0490x over previous
#include <cuda_runtime.h>
#include <cuda_fp16.h>
#include <math.h>
#include <stdint.h>

#define E_N 64
#define H_N 512
#define F_N 2048
#define T_N 2048
#define KSPLIT 4         // phase-2 K segments
#define HB_STRIDE 3072   // padded token columns across all experts

// Scratch (device globals; zero-initialized at module load).
__device__ float g_hbufT[(size_t)F_N * HB_STRIDE];            // 24 MB [f][tok]
__device__ float g_part[(size_t)KSPLIT * T_N * H_N];          // 16 MB [seg][t][h]

__device__ __forceinline__ float gelu_exact(float v) {
    return 0.5f * v * (1.0f + erff(v * 0.70710678118654752f));
}
// Pack two fp32 into half2: lo = a, hi = b.
__device__ __forceinline__ uint32_t pack2(float a, float b) {
    uint32_t u;
    asm("cvt.rn.f16x2.f32 %0, %1, %2;" : "=r"(u) : "f"(b), "f"(a));
    return u;
}
__device__ __forceinline__ void mma16(float c[4], uint32_t a0, uint32_t a1,
                                      uint32_t a2, uint32_t a3,
                                      uint32_t b0, uint32_t b1) {
    asm volatile(
        "mma.sync.aligned.m16n8k16.row.col.f32.f16.f16.f32 "
        "{%0,%1,%2,%3},{%4,%5,%6,%7},{%8,%9},{%0,%1,%2,%3};"
        : "+f"(c[0]), "+f"(c[1]), "+f"(c[2]), "+f"(c[3])
        : "r"(a0), "r"(a1), "r"(a2), "r"(a3), "r"(b0), "r"(b1));
}
__device__ __forceinline__ void cp16(uint32_t dst, const void* src) {
    asm volatile("cp.async.cg.shared.global [%0], [%1], 16;"
                 :: "r"(dst), "l"(src) : "memory");
}
__device__ __forceinline__ void cp_commit() {
    asm volatile("cp.async.commit_group;" ::: "memory");
}
template <int N>
__device__ __forceinline__ void cp_wait() {
    asm volatile("cp.async.wait_group %0;" :: "n"(N) : "memory");
}

// ---------------------------------------------------------------------------
// 256 threads, BM=128 (one 16-row m-block per warp), BN=48, BK=32.
// A tiles (weights): fp32 in smem via cp.async, 4 slots of 16 KB:
//   PHASE 1 [m 128][k 32]: byte(m,k) = m*128 + ((k>>2)^(m&7))*16 + (k&3)*4
//   PHASE 2 [k 32][h 128]: byte(k,h) = k*512 + ((h>>2)^(k&7))*16 + (h&3)*4
// B tiles: fp16 fragment-pair layout, 2 buffers.
// Schedule (one __syncthreads per chunk):
//   iter c: wait_group(2); bar; stsB(c+1); ldB(c+3); cpA(c+3); commit; MMA(c)
// PHASE 2 is split-K: blockIdx.z = segment of 512 k; partials -> g_part[seg].
// ---------------------------------------------------------------------------
#define A_SLOT_B 16384
#define BSZ_U32 (6 * 2 * 66)
#define SMEM_BYTES (4 * A_SLOT_B + 2 * BSZ_U32 * 4)   // 71872 -> 3 CTAs/SM

template <int PHASE>
__global__ void __launch_bounds__(256)
mlp_kernel(const float* __restrict__ x, const float* __restrict__ wgt,
           const int* __restrict__ counts) {
    constexpr int NCH = 16;   // both phases: 16 chunks of 32 k per CTA

    extern __shared__ __align__(16) uint8_t smem_raw[];
    uint8_t*  Ab  = smem_raw;                               // 4 fp32 A slots
    uint32_t* Bh  = (uint32_t*)(smem_raw + 4 * A_SLOT_B);   // 2 fp16 B bufs
    const uint32_t aAddr = (uint32_t)__cvta_generic_to_shared(Ab);

    const int tid = threadIdx.x;
    const int w = tid >> 5, lane = tid & 31;
    const int g = lane >> 2, tg = lane & 3;
    const int e = blockIdx.y;
    const int mbase = blockIdx.x * 128;
    const int kseg  = (PHASE == 2) ? blockIdx.z * 512 : 0;   // K segment base

    // ---- in-kernel scan of tokens_per_expert (warp 0) ----
    __shared__ int s_sc[3];
    if (tid < 32) {
        const unsigned FULL = 0xffffffffu;
        int c0 = counts[lane], c1 = counts[lane + 32];
        int p0 = (c0 + 15) & ~15, p1 = (c1 + 15) & ~15;
        int i0 = c0, i1 = c1, q0 = p0, q1 = p1;
        #pragma unroll
        for (int d = 1; d < 32; d <<= 1) {
            int t;
            t = __shfl_up_sync(FULL, i0, d); if (lane >= d) i0 += t;
            t = __shfl_up_sync(FULL, i1, d); if (lane >= d) i1 += t;
            t = __shfl_up_sync(FULL, q0, d); if (lane >= d) q0 += t;
            t = __shfl_up_sync(FULL, q1, d); if (lane >= d) q1 += t;
        }
        int tot0  = __shfl_sync(FULL, i0, 31);
        int ptot0 = __shfl_sync(FULL, q0, 31);
        int el = e & 31, ex, cc, pex;
        if (e < 32) {
            ex  = __shfl_sync(FULL, i0, el) - __shfl_sync(FULL, c0, el);
            cc  = __shfl_sync(FULL, c0, el);
            pex = __shfl_sync(FULL, q0, el) - __shfl_sync(FULL, p0, el);
        } else {
            ex  = tot0 + __shfl_sync(FULL, i1, el) - __shfl_sync(FULL, c1, el);
            cc  = __shfl_sync(FULL, c1, el);
            pex = ptot0 + __shfl_sync(FULL, q1, el) - __shfl_sync(FULL, p1, el);
        }
        if (lane == 0) { s_sc[0] = ex; s_sc[1] = cc; s_sc[2] = pex; }
    }
    __syncthreads();
    const int toff = s_sc[0], cnt = s_sc[1], poff = s_sc[2];
    const float* we = wgt + (size_t)e * F_N * H_N;

    float4 rB[2][2];

    for (int tbase = 0; tbase < cnt; tbase += 48) {
        const int nlim = (cnt - tbase < 48) ? (cnt - tbase) : 48;
        const int nbl  = (nlim + 7) >> 3;

        // ---- A producer: cp.async chunk c -> slot (4 x 16B per thread) ----
        auto cpA = [&](int slot, int c) {
            const int k0 = kseg + c * 32;
            const uint32_t sb = aAddr + slot * A_SLOT_B;
            #pragma unroll
            for (int i = 0; i < 4; ++i) {
                int q = tid + i * 256;
                if (PHASE == 1) {
                    int m = q >> 3, u = q & 7;       // u: 16B chunk along k
                    cp16(sb + m * 128 + ((u ^ (m & 7)) << 4),
                         we + (size_t)(mbase + m) * H_N + k0 + u * 4);
                } else {
                    int k = q >> 5, u = q & 31;      // u: 16B chunk along h
                    cp16(sb + k * 512 + ((u ^ (k & 7)) << 4),
                         we + (size_t)(k0 + k) * H_N + mbase + u * 4);
                }
            }
        };
        // ---- B producer: gmem -> regs ----
        auto ldB = [&](int set, int c) {
            const int k0 = kseg + c * 32;
            if (PHASE == 1) {
                #pragma unroll
                for (int i = 0; i < 2; ++i) {      // 48 t x 8 k4 = 384 slots
                    int q = tid + i * 256;
                    if (q < 384) {
                        int t = q >> 3, k4 = q & 7;
                        if (tbase + t < cnt)
                            rB[set][i] = *(const float4*)&x[(size_t)(toff + tbase + t) * H_N + k0 + k4 * 4];
                        else
                            rB[set][i] = make_float4(0.f, 0.f, 0.f, 0.f);
                    }
                }
            } else {
                int q = tid;                        // 12 n4 x 16 kp = 192 slots
                if (q < 192) {
                    int n4 = q % 12, kp = q / 12;
                    const float* p0 = &g_hbufT[(size_t)(k0 + 2 * kp) * HB_STRIDE +
                                               poff + tbase + n4 * 4];
                    rB[set][0] = *(const float4*)p0;
                    rB[set][1] = *(const float4*)(p0 + HB_STRIDE);
                }
            }
        };
        auto bidx = [](int n, int p) {
            int pb = p & 7;
            return ((n >> 3) * 2 + (p >> 3)) * 66 + (n & 7) * 8 + (pb & 3) * 2 + (pb >> 2);
        };
        auto stsB = [&](int buf, int set) {
            uint32_t* Bs = Bh + buf * BSZ_U32;
            if (PHASE == 1) {
                #pragma unroll
                for (int i = 0; i < 2; ++i) {
                    int q = tid + i * 256;
                    if (q < 384) {
                        int t = q >> 3, k4 = q & 7;
                        Bs[bidx(t, 2 * k4)]     = pack2(rB[set][i].x, rB[set][i].y);
                        Bs[bidx(t, 2 * k4 + 1)] = pack2(rB[set][i].z, rB[set][i].w);
                    }
                }
            } else {
                int q = tid;
                if (q < 192) {
                    int n4 = q % 12, kp = q / 12;
                    const float* a = (const float*)&rB[set][0];
                    const float* b = (const float*)&rB[set][1];
                    #pragma unroll
                    for (int j = 0; j < 4; ++j)
                        Bs[bidx(n4 * 4 + j, kp)] = pack2(a[j], b[j]);
                }
            }
        };

        float acc[6][4];
        #pragma unroll
        for (int nb = 0; nb < 6; ++nb)
            #pragma unroll
            for (int r = 0; r < 4; ++r) acc[nb][r] = 0.f;

        // -------- prologue --------
        ldB(0, 0); ldB(1, 1);
        stsB(0, 0);
        ldB(0, 2);
        cpA(0, 0); cp_commit();
        cpA(1, 1); cp_commit();
        cpA(2, 2); cp_commit();
        __syncthreads();

        // -------- mainloop: one barrier per chunk --------
        for (int c = 0; c < NCH; ++c) {
            cp_wait<2>();
            __syncthreads();
            if (c + 1 < NCH) stsB((c + 1) & 1, (c + 1) & 1);
            if (c + 3 < NCH) { ldB((c + 3) & 1, c + 3); cpA((c + 3) & 3, c + 3); }
            cp_commit();

            const uint8_t*  As = Ab + (c & 3) * A_SLOT_B;
            const uint32_t* Bs = Bh + (c & 1) * BSZ_U32;
            const int m0 = w * 16 + g;
            #pragma unroll
            for (int kb = 0; kb < 2; ++kb) {
                const int k = 2 * tg + 16 * kb;
                uint32_t a[4];
                if (PHASE == 1) {
                    auto ld2 = [&](int m, int kk) -> float2 {
                        int off = m * 128 + (((kk >> 2) ^ (m & 7)) << 4) + ((kk & 3) << 2);
                        return *(const float2*)(As + off);
                    };
                    float2 v00 = ld2(m0, k),     v10 = ld2(m0 + 8, k);
                    float2 v01 = ld2(m0, k + 8), v11 = ld2(m0 + 8, k + 8);
                    a[0] = pack2(v00.x, v00.y);
                    a[1] = pack2(v10.x, v10.y);
                    a[2] = pack2(v01.x, v01.y);
                    a[3] = pack2(v11.x, v11.y);
                } else {
                    auto ld1 = [&](int kk, int h) -> float {
                        int off = kk * 512 + (((h >> 2) ^ (kk & 7)) << 4) + ((h & 3) << 2);
                        return *(const float*)(As + off);
                    };
                    a[0] = pack2(ld1(k, m0),     ld1(k + 1, m0));
                    a[1] = pack2(ld1(k, m0 + 8), ld1(k + 1, m0 + 8));
                    a[2] = pack2(ld1(k + 8, m0),     ld1(k + 9, m0));
                    a[3] = pack2(ld1(k + 8, m0 + 8), ld1(k + 9, m0 + 8));
                }
                #pragma unroll
                for (int nb = 0; nb < 6; ++nb) {
                    if (nb < nbl) {
                        const uint32_t* bb = &Bs[(nb * 2 + kb) * 66];
                        uint2 pb = *(const uint2*)&bb[2 * lane];
                        mma16(acc[nb], a[0], a[1], a[2], a[3], pb.x, pb.y);
                    }
                }
            }
            __syncthreads();
        }
        cp_wait<0>();

        // -------- epilogue --------
        {
            const int r0 = mbase + w * 16 + g;
            const int r1 = r0 + 8;
            float* pout = g_part + (size_t)((PHASE == 2) ? blockIdx.z : 0) * T_N * H_N;
            #pragma unroll
            for (int nb = 0; nb < 6; ++nb) {
                const int n0 = nb * 8 + tg * 2;
                const float* c4 = acc[nb];
                if (PHASE == 1) {
                    size_t b0 = (size_t)r0 * HB_STRIDE + poff + tbase + n0;
                    size_t b1 = (size_t)r1 * HB_STRIDE + poff + tbase + n0;
                    if (n0 + 1 < nlim) {
                        *(float2*)&g_hbufT[b0] = make_float2(gelu_exact(c4[0]), gelu_exact(c4[1]));
                        *(float2*)&g_hbufT[b1] = make_float2(gelu_exact(c4[2]), gelu_exact(c4[3]));
                    } else if (n0 < nlim) {
                        g_hbufT[b0] = gelu_exact(c4[0]);
                        g_hbufT[b1] = gelu_exact(c4[2]);
                    }
                } else {
                    const int t0 = toff + tbase + n0;
                    if (n0 < nlim) {
                        pout[(size_t)t0 * H_N + r0] = c4[0];
                        pout[(size_t)t0 * H_N + r1] = c4[2];
                    }
                    if (n0 + 1 < nlim) {
                        pout[(size_t)(t0 + 1) * H_N + r0] = c4[1];
                        pout[(size_t)(t0 + 1) * H_N + r1] = c4[3];
                    }
                }
            }
        }
        __syncthreads();  // smem reuse across token tiles
    }
}

// Deterministic split-K reduction: out[t,h] = sum over KSPLIT partials.
__global__ void __launch_bounds__(256)
reduce_kernel(float* __restrict__ outp) {
    const size_t i = (size_t)blockIdx.x * 256 + threadIdx.x;   // float4 index
    const size_t NV = (size_t)T_N * H_N / 4;
    if (i < NV) {
        const float4* p = (const float4*)g_part;
        float4 a = p[i];
        #pragma unroll
        for (int s = 1; s < KSPLIT; ++s) {
            float4 b = p[i + s * NV];
            a.x += b.x; a.y += b.y; a.z += b.z; a.w += b.w;
        }
        ((float4*)outp)[i] = a;
    }
}

// ---------------------------------------------------------------------------
// Inputs: d_in[0]=x [T,H] f32, d_in[1]=w1 [E,F,H] f32, d_in[2]=w2 [E,F,H] f32,
//         d_in[3]=tokens_per_expert [E] i32.  d_out=[T,H] f32.
// ---------------------------------------------------------------------------
extern "C" void kernel_launch(void* const* d_in, const int* in_sizes, int n_in,
                              void* d_out, int out_size) {
    const float* x      = (const float*)d_in[0];
    const float* w1     = (const float*)d_in[1];
    const float* w2     = (const float*)d_in[2];
    const int*   counts = (const int*)d_in[3];
    float* out = (float*)d_out;

    cudaFuncSetAttribute(mlp_kernel<1>, cudaFuncAttributeMaxDynamicSharedMemorySize, SMEM_BYTES);
    cudaFuncSetAttribute(mlp_kernel<2>, cudaFuncAttributeMaxDynamicSharedMemorySize, SMEM_BYTES);

    mlp_kernel<1><<<dim3(F_N / 128, E_N, 1), 256, SMEM_BYTES>>>(x, w1, counts);
    mlp_kernel<2><<<dim3(H_N / 128, E_N, KSPLIT), 256, SMEM_BYTES>>>(x, w2, counts);
    reduce_kernel<<<(T_N * H_N / 4 + 255) / 256, 256>>>(out);
}

// round 13
// speedup vs baseline: 1.3413x; 1.2787x over previous
#include <cuda_runtime.h>
#include <cuda_fp16.h>
#include <math.h>
#include <stdint.h>

#define E_N 64
#define H_N 512
#define F_N 2048
#define T_N 2048
#define KSPLIT 4         // phase-2 K segments
#define HB_STRIDE 3072   // padded token columns across all experts

// Scratch (device globals; zero-initialized at module load).
__device__ float g_hbufT[(size_t)F_N * HB_STRIDE];            // 24 MB [f][tok]
__device__ float g_part[(size_t)KSPLIT * T_N * H_N];          // 16 MB [seg][t][h]

__device__ __forceinline__ float gelu_exact(float v) {
    return 0.5f * v * (1.0f + erff(v * 0.70710678118654752f));
}
// Pack two fp32 into half2: lo = a, hi = b.
__device__ __forceinline__ uint32_t pack2(float a, float b) {
    uint32_t u;
    asm("cvt.rn.f16x2.f32 %0, %1, %2;" : "=r"(u) : "f"(b), "f"(a));
    return u;
}
__device__ __forceinline__ void mma16(float c[4], uint32_t a0, uint32_t a1,
                                      uint32_t a2, uint32_t a3,
                                      uint32_t b0, uint32_t b1) {
    asm volatile(
        "mma.sync.aligned.m16n8k16.row.col.f32.f16.f16.f32 "
        "{%0,%1,%2,%3},{%4,%5,%6,%7},{%8,%9},{%0,%1,%2,%3};"
        : "+f"(c[0]), "+f"(c[1]), "+f"(c[2]), "+f"(c[3])
        : "r"(a0), "r"(a1), "r"(a2), "r"(a3), "r"(b0), "r"(b1));
}
__device__ __forceinline__ void cp16(uint32_t dst, const void* src) {
    asm volatile("cp.async.cg.shared.global [%0], [%1], 16;"
                 :: "r"(dst), "l"(src) : "memory");
}
__device__ __forceinline__ void cp_commit() {
    asm volatile("cp.async.commit_group;" ::: "memory");
}
template <int N>
__device__ __forceinline__ void cp_wait() {
    asm volatile("cp.async.wait_group %0;" :: "n"(N) : "memory");
}
// fp16 fragment-pair B layout index (u32 units).
__device__ __forceinline__ uint32_t bidx(int n, int p) {
    int pb = p & 7;
    return ((n >> 3) * 2 + (p >> 3)) * 66 + (n & 7) * 8 + (pb & 3) * 2 + (pb >> 2);
}

// ---------------------------------------------------------------------------
// 256 threads, 3 CTAs/SM (reg-capped), BM=128 (one m-block per warp), BN=48,
// BK=32. A (weights): fp32 via cp.async, 4 slots of 16 KB, XOR-swizzled.
// B: fp16 fragment-pair layout, 2 buffers, reg-staged 2 chunks ahead.
// One __syncthreads per chunk:
//   iter c: wait_group(2); bar; stsB(c+1); ldB(c+3); cpA(c+3); commit; MMA(c)
// PHASE 2 split-K: blockIdx.z = 512-k segment; partials -> g_part[seg].
// ---------------------------------------------------------------------------
#define A_SLOT_B 16384
#define BSZ_U32 (6 * 2 * 66)
#define SMEM_BYTES (4 * A_SLOT_B + 2 * BSZ_U32 * 4)   // 71872

template <int PHASE>
__global__ void __launch_bounds__(256, 3)
mlp_kernel(const float* __restrict__ x, const float* __restrict__ wgt,
           const int* __restrict__ counts) {
    constexpr int NCH = 16;   // both phases: 16 chunks of 32 k per CTA

    extern __shared__ __align__(16) uint8_t smem_raw[];
    uint8_t*  Ab  = smem_raw;                               // 4 fp32 A slots
    uint32_t* Bh  = (uint32_t*)(smem_raw + 4 * A_SLOT_B);   // 2 fp16 B bufs
    const uint32_t aAddr = (uint32_t)__cvta_generic_to_shared(Ab);

    const int tid = threadIdx.x;
    const int w = tid >> 5, lane = tid & 31;
    const int g = lane >> 2, tg = lane & 3;
    const int e = blockIdx.y;
    const int mbase = blockIdx.x * 128;
    const int kseg  = (PHASE == 2) ? blockIdx.z * 512 : 0;

    // ---- in-kernel scan of tokens_per_expert (warp 0) ----
    __shared__ int s_sc[3];
    if (tid < 32) {
        const unsigned FULL = 0xffffffffu;
        int c0 = counts[lane], c1 = counts[lane + 32];
        int p0 = (c0 + 15) & ~15, p1 = (c1 + 15) & ~15;
        int i0 = c0, i1 = c1, q0 = p0, q1 = p1;
        #pragma unroll
        for (int d = 1; d < 32; d <<= 1) {
            int t;
            t = __shfl_up_sync(FULL, i0, d); if (lane >= d) i0 += t;
            t = __shfl_up_sync(FULL, i1, d); if (lane >= d) i1 += t;
            t = __shfl_up_sync(FULL, q0, d); if (lane >= d) q0 += t;
            t = __shfl_up_sync(FULL, q1, d); if (lane >= d) q1 += t;
        }
        int tot0  = __shfl_sync(FULL, i0, 31);
        int ptot0 = __shfl_sync(FULL, q0, 31);
        int el = e & 31, ex, cc, pex;
        if (e < 32) {
            ex  = __shfl_sync(FULL, i0, el) - __shfl_sync(FULL, c0, el);
            cc  = __shfl_sync(FULL, c0, el);
            pex = __shfl_sync(FULL, q0, el) - __shfl_sync(FULL, p0, el);
        } else {
            ex  = tot0 + __shfl_sync(FULL, i1, el) - __shfl_sync(FULL, c1, el);
            cc  = __shfl_sync(FULL, c1, el);
            pex = ptot0 + __shfl_sync(FULL, q1, el) - __shfl_sync(FULL, p1, el);
        }
        if (lane == 0) { s_sc[0] = ex; s_sc[1] = cc; s_sc[2] = pex; }
    }
    __syncthreads();
    const int toff = s_sc[0], cnt = s_sc[1], poff = s_sc[2];
    const float* we = wgt + (size_t)e * F_N * H_N;

    // ---- loop-invariant per-thread loader state ----
    uint32_t cpaOff[4]; const float* cpaSrc[4];
    #pragma unroll
    for (int i = 0; i < 4; ++i) {
        int q = tid + i * 256;
        if (PHASE == 1) {
            int m = q >> 3, u = q & 7;
            cpaOff[i] = (uint32_t)(m * 128 + ((u ^ (m & 7)) << 4));
            cpaSrc[i] = we + (size_t)(mbase + m) * H_N + u * 4;
        } else {
            int k = q >> 5, u = q & 31;
            cpaOff[i] = (uint32_t)(k * 512 + ((u ^ (k & 7)) << 4));
            cpaSrc[i] = we + (size_t)k * H_N + mbase + u * 4;
        }
    }
    // B indices (phase-dependent)
    int bt0 = 0, bt1 = 0;                 // phase1 token rows for slots 0,1
    uint32_t bOff[2][2];                  // phase1 STS offsets
    int n4 = 0, kp = 0; uint32_t bOff2[4];// phase2
    if (PHASE == 1) {
        #pragma unroll
        for (int i = 0; i < 2; ++i) {
            int q = tid + i * 256;
            int qq = (q < 384) ? q : 0;
            int t = qq >> 3, k4 = qq & 7;
            if (i == 0) bt0 = t; else bt1 = t;
            bOff[i][0] = bidx(t, 2 * k4);
            bOff[i][1] = bidx(t, 2 * k4 + 1);
        }
    } else {
        n4 = tid % 12; kp = tid / 12;
        #pragma unroll
        for (int j = 0; j < 4; ++j) bOff2[j] = bidx(n4 * 4 + j, kp);
    }

    float4 rB[2][2];

    for (int tbase = 0; tbase < cnt; tbase += 48) {
        const int nlim = (cnt - tbase < 48) ? (cnt - tbase) : 48;
        const int nbl  = (nlim + 7) >> 3;

        // phase-2 B gmem base for this token tile (k0 added per chunk)
        const float* b2src = (PHASE == 2)
            ? g_hbufT + (size_t)(kseg + 2 * kp) * HB_STRIDE + poff + tbase + n4 * 4
            : nullptr;

        auto cpA = [&](int slot, int c) {
            const int k0 = c * 32;
            const uint32_t sb = aAddr + slot * A_SLOT_B;
            #pragma unroll
            for (int i = 0; i < 4; ++i) {
                const float* src = (PHASE == 1) ? cpaSrc[i] + kseg + k0
                                                : cpaSrc[i] + (size_t)(kseg + k0) * H_N;
                cp16(sb + cpaOff[i], src);
            }
        };
        auto ldB = [&](int set, int c) {
            const int k0 = c * 32;
            if (PHASE == 1) {
                {   // slot 0: q = tid < 384 always
                    if (tbase + bt0 < cnt)
                        rB[set][0] = *(const float4*)&x[(size_t)(toff + tbase + bt0) * H_N + k0 + (tid & 7) * 4];
                    else
                        rB[set][0] = make_float4(0.f, 0.f, 0.f, 0.f);
                }
                if (tid < 128) {   // slot 1: q = tid+256 < 384
                    if (tbase + bt1 < cnt)
                        rB[set][1] = *(const float4*)&x[(size_t)(toff + tbase + bt1) * H_N + k0 + (tid & 7) * 4];
                    else
                        rB[set][1] = make_float4(0.f, 0.f, 0.f, 0.f);
                }
            } else {
                if (tid < 192) {
                    const float* p0 = b2src + (size_t)k0 * HB_STRIDE;
                    rB[set][0] = *(const float4*)p0;
                    rB[set][1] = *(const float4*)(p0 + HB_STRIDE);
                }
            }
        };
        auto stsB = [&](int buf, int set) {
            uint32_t* Bs = Bh + buf * BSZ_U32;
            if (PHASE == 1) {
                Bs[bOff[0][0]] = pack2(rB[set][0].x, rB[set][0].y);
                Bs[bOff[0][1]] = pack2(rB[set][0].z, rB[set][0].w);
                if (tid < 128) {
                    Bs[bOff[1][0]] = pack2(rB[set][1].x, rB[set][1].y);
                    Bs[bOff[1][1]] = pack2(rB[set][1].z, rB[set][1].w);
                }
            } else {
                if (tid < 192) {
                    const float* a = (const float*)&rB[set][0];
                    const float* b = (const float*)&rB[set][1];
                    #pragma unroll
                    for (int j = 0; j < 4; ++j)
                        Bs[bOff2[j]] = pack2(a[j], b[j]);
                }
            }
        };

        float acc[6][4];
        #pragma unroll
        for (int nb = 0; nb < 6; ++nb)
            #pragma unroll
            for (int r = 0; r < 4; ++r) acc[nb][r] = 0.f;

        // -------- prologue --------
        ldB(0, 0); ldB(1, 1);
        stsB(0, 0);
        ldB(0, 2);
        cpA(0, 0); cp_commit();
        cpA(1, 1); cp_commit();
        cpA(2, 2); cp_commit();
        __syncthreads();

        // -------- mainloop: one barrier per chunk --------
        #pragma unroll 4
        for (int c = 0; c < NCH; ++c) {
            cp_wait<2>();
            __syncthreads();
            if (c + 1 < NCH) stsB((c + 1) & 1, (c + 1) & 1);
            if (c + 3 < NCH) { ldB((c + 3) & 1, c + 3); cpA((c + 3) & 3, c + 3); }
            cp_commit();

            const uint8_t*  As = Ab + (c & 3) * A_SLOT_B;
            const uint32_t* Bs = Bh + (c & 1) * BSZ_U32;
            const int m0 = w * 16 + g;
            #pragma unroll
            for (int kb = 0; kb < 2; ++kb) {
                const int k = 2 * tg + 16 * kb;
                uint32_t a[4];
                if (PHASE == 1) {
                    auto ld2 = [&](int m, int kk) -> float2 {
                        int off = m * 128 + (((kk >> 2) ^ (m & 7)) << 4) + ((kk & 3) << 2);
                        return *(const float2*)(As + off);
                    };
                    float2 v00 = ld2(m0, k),     v10 = ld2(m0 + 8, k);
                    float2 v01 = ld2(m0, k + 8), v11 = ld2(m0 + 8, k + 8);
                    a[0] = pack2(v00.x, v00.y);
                    a[1] = pack2(v10.x, v10.y);
                    a[2] = pack2(v01.x, v01.y);
                    a[3] = pack2(v11.x, v11.y);
                } else {
                    auto ld1 = [&](int kk, int h) -> float {
                        int off = kk * 512 + (((h >> 2) ^ (kk & 7)) << 4) + ((h & 3) << 2);
                        return *(const float*)(As + off);
                    };
                    a[0] = pack2(ld1(k, m0),     ld1(k + 1, m0));
                    a[1] = pack2(ld1(k, m0 + 8), ld1(k + 1, m0 + 8));
                    a[2] = pack2(ld1(k + 8, m0),     ld1(k + 9, m0));
                    a[3] = pack2(ld1(k + 8, m0 + 8), ld1(k + 9, m0 + 8));
                }
                #pragma unroll
                for (int nb = 0; nb < 6; ++nb) {
                    if (nb < nbl) {
                        const uint32_t* bb = &Bs[(nb * 2 + kb) * 66];
                        uint2 pb = *(const uint2*)&bb[2 * lane];
                        mma16(acc[nb], a[0], a[1], a[2], a[3], pb.x, pb.y);
                    }
                }
            }
            __syncthreads();
        }
        cp_wait<0>();

        // -------- epilogue --------
        {
            const int r0 = mbase + w * 16 + g;
            const int r1 = r0 + 8;
            float* pout = g_part + (size_t)((PHASE == 2) ? blockIdx.z : 0) * T_N * H_N;
            #pragma unroll
            for (int nb = 0; nb < 6; ++nb) {
                const int n0 = nb * 8 + tg * 2;
                const float* c4 = acc[nb];
                if (PHASE == 1) {
                    size_t b0 = (size_t)r0 * HB_STRIDE + poff + tbase + n0;
                    size_t b1 = (size_t)r1 * HB_STRIDE + poff + tbase + n0;
                    if (n0 + 1 < nlim) {
                        *(float2*)&g_hbufT[b0] = make_float2(gelu_exact(c4[0]), gelu_exact(c4[1]));
                        *(float2*)&g_hbufT[b1] = make_float2(gelu_exact(c4[2]), gelu_exact(c4[3]));
                    } else if (n0 < nlim) {
                        g_hbufT[b0] = gelu_exact(c4[0]);
                        g_hbufT[b1] = gelu_exact(c4[2]);
                    }
                } else {
                    const int t0 = toff + tbase + n0;
                    if (n0 < nlim) {
                        pout[(size_t)t0 * H_N + r0] = c4[0];
                        pout[(size_t)t0 * H_N + r1] = c4[2];
                    }
                    if (n0 + 1 < nlim) {
                        pout[(size_t)(t0 + 1) * H_N + r0] = c4[1];
                        pout[(size_t)(t0 + 1) * H_N + r1] = c4[3];
                    }
                }
            }
        }
        __syncthreads();  // smem reuse across token tiles
    }
}

// Deterministic split-K reduction: out[t,h] = sum over KSPLIT partials.
__global__ void __launch_bounds__(256)
reduce_kernel(float* __restrict__ outp) {
    const size_t i = (size_t)blockIdx.x * 256 + threadIdx.x;   // float4 index
    const size_t NV = (size_t)T_N * H_N / 4;
    if (i < NV) {
        const float4* p = (const float4*)g_part;
        float4 a = p[i];
        #pragma unroll
        for (int s = 1; s < KSPLIT; ++s) {
            float4 b = p[i + s * NV];
            a.x += b.x; a.y += b.y; a.z += b.z; a.w += b.w;
        }
        ((float4*)outp)[i] = a;
    }
}

// ---------------------------------------------------------------------------
// Inputs: d_in[0]=x [T,H] f32, d_in[1]=w1 [E,F,H] f32, d_in[2]=w2 [E,F,H] f32,
//         d_in[3]=tokens_per_expert [E] i32.  d_out=[T,H] f32.
// ---------------------------------------------------------------------------
extern "C" void kernel_launch(void* const* d_in, const int* in_sizes, int n_in,
                              void* d_out, int out_size) {
    const float* x      = (const float*)d_in[0];
    const float* w1     = (const float*)d_in[1];
    const float* w2     = (const float*)d_in[2];
    const int*   counts = (const int*)d_in[3];
    float* out = (float*)d_out;

    cudaFuncSetAttribute(mlp_kernel<1>, cudaFuncAttributeMaxDynamicSharedMemorySize, SMEM_BYTES);
    cudaFuncSetAttribute(mlp_kernel<2>, cudaFuncAttributeMaxDynamicSharedMemorySize, SMEM_BYTES);

    mlp_kernel<1><<<dim3(F_N / 128, E_N, 1), 256, SMEM_BYTES>>>(x, w1, counts);
    mlp_kernel<2><<<dim3(H_N / 128, E_N, KSPLIT), 256, SMEM_BYTES>>>(x, w2, counts);
    reduce_kernel<<<(T_N * H_N / 4 + 255) / 256, 256>>>(out);
}

// round 14
// speedup vs baseline: 1.3874x; 1.0343x over previous
#include <cuda_runtime.h>
#include <cuda_fp16.h>
#include <math.h>
#include <stdint.h>

#define E_N 64
#define H_N 512
#define F_N 2048
#define T_N 2048
#define KSPLIT 4         // phase-2 K segments
#define HB_STRIDE 3072   // padded token columns across all experts

// Scratch (device globals; zero-initialized at module load).
__device__ float g_hbufT[(size_t)F_N * HB_STRIDE];            // 24 MB [f][tok]
__device__ float g_part[(size_t)KSPLIT * T_N * H_N];          // 16 MB [seg][t][h]

__device__ __forceinline__ float gelu_exact(float v) {
    return 0.5f * v * (1.0f + erff(v * 0.70710678118654752f));
}
// Pack two fp32 into half2: lo = a, hi = b.
__device__ __forceinline__ uint32_t pack2(float a, float b) {
    uint32_t u;
    asm("cvt.rn.f16x2.f32 %0, %1, %2;" : "=r"(u) : "f"(b), "f"(a));
    return u;
}
__device__ __forceinline__ void mma16(float c[4], uint32_t a0, uint32_t a1,
                                      uint32_t a2, uint32_t a3,
                                      uint32_t b0, uint32_t b1) {
    asm volatile(
        "mma.sync.aligned.m16n8k16.row.col.f32.f16.f16.f32 "
        "{%0,%1,%2,%3},{%4,%5,%6,%7},{%8,%9},{%0,%1,%2,%3};"
        : "+f"(c[0]), "+f"(c[1]), "+f"(c[2]), "+f"(c[3])
        : "r"(a0), "r"(a1), "r"(a2), "r"(a3), "r"(b0), "r"(b1));
}
__device__ __forceinline__ void cp16(uint32_t dst, const void* src) {
    asm volatile("cp.async.cg.shared.global [%0], [%1], 16;"
                 :: "r"(dst), "l"(src) : "memory");
}
__device__ __forceinline__ void cp_commit() {
    asm volatile("cp.async.commit_group;" ::: "memory");
}
template <int N>
__device__ __forceinline__ void cp_wait() {
    asm volatile("cp.async.wait_group %0;" :: "n"(N) : "memory");
}
// fp16 fragment-pair B layout index (u32 units).
__device__ __forceinline__ uint32_t bidx(int n, int p) {
    int pb = p & 7;
    return ((n >> 3) * 2 + (p >> 3)) * 66 + (n & 7) * 8 + (pb & 3) * 2 + (pb >> 2);
}

// ---------------------------------------------------------------------------
// 256 threads, 4 CTAs/SM target, BM=128 (one m-block per warp), BN=48, BK=32.
// A (weights): fp32 via cp.async, 3 slots of 16 KB, XOR-swizzled. Per-thread
// cp.async addressing is a single base + 4096 B stride (both phases).
// B: fp16 fragment-pair layout, 2 buffers, reg-staged 2 chunks ahead.
// Per chunk: wait<2>; bar; stsB(c+1); ldB(c+3); MMA(c); bar; cpA(c+3); commit.
// Pending cp groups held at 3 (empty commits at tail) so wait<2> pins slot c.
// PHASE 2 split-K: blockIdx.z = 512-k segment; partials -> g_part[seg].
// ---------------------------------------------------------------------------
#define A_SLOT_B 16384
#define BSZ_U32 (6 * 2 * 66)
#define SMEM_BYTES (3 * A_SLOT_B + 2 * BSZ_U32 * 4)   // 55488 -> 4 CTAs/SM

template <int PHASE>
__global__ void __launch_bounds__(256, 4)
mlp_kernel(const float* __restrict__ x, const float* __restrict__ wgt,
           const int* __restrict__ counts) {
    constexpr int NCH = 16;   // both phases: 16 chunks of 32 k per CTA

    extern __shared__ __align__(16) uint8_t smem_raw[];
    uint8_t*  Ab  = smem_raw;                               // 3 fp32 A slots
    uint32_t* Bh  = (uint32_t*)(smem_raw + 3 * A_SLOT_B);   // 2 fp16 B bufs
    const uint32_t aAddr = (uint32_t)__cvta_generic_to_shared(Ab);

    const int tid = threadIdx.x;
    const int w = tid >> 5, lane = tid & 31;
    const int g = lane >> 2, tg = lane & 3;
    const int e = blockIdx.y;
    const int mbase = blockIdx.x * 128;
    const int kseg  = (PHASE == 2) ? blockIdx.z * 512 : 0;

    // ---- in-kernel scan of tokens_per_expert (warp 0) ----
    __shared__ int s_sc[3];
    if (tid < 32) {
        const unsigned FULL = 0xffffffffu;
        int c0 = counts[lane], c1 = counts[lane + 32];
        int p0 = (c0 + 15) & ~15, p1 = (c1 + 15) & ~15;
        int i0 = c0, i1 = c1, q0 = p0, q1 = p1;
        #pragma unroll
        for (int d = 1; d < 32; d <<= 1) {
            int t;
            t = __shfl_up_sync(FULL, i0, d); if (lane >= d) i0 += t;
            t = __shfl_up_sync(FULL, i1, d); if (lane >= d) i1 += t;
            t = __shfl_up_sync(FULL, q0, d); if (lane >= d) q0 += t;
            t = __shfl_up_sync(FULL, q1, d); if (lane >= d) q1 += t;
        }
        int tot0  = __shfl_sync(FULL, i0, 31);
        int ptot0 = __shfl_sync(FULL, q0, 31);
        int el = e & 31, ex, cc, pex;
        if (e < 32) {
            ex  = __shfl_sync(FULL, i0, el) - __shfl_sync(FULL, c0, el);
            cc  = __shfl_sync(FULL, c0, el);
            pex = __shfl_sync(FULL, q0, el) - __shfl_sync(FULL, p0, el);
        } else {
            ex  = tot0 + __shfl_sync(FULL, i1, el) - __shfl_sync(FULL, c1, el);
            cc  = __shfl_sync(FULL, c1, el);
            pex = ptot0 + __shfl_sync(FULL, q1, el) - __shfl_sync(FULL, p1, el);
        }
        if (lane == 0) { s_sc[0] = ex; s_sc[1] = cc; s_sc[2] = pex; }
    }
    __syncthreads();
    const int toff = s_sc[0], cnt = s_sc[1], poff = s_sc[2];
    const float* we = wgt + (size_t)e * F_N * H_N;

    // ---- loop-invariant loader state (single base + 4096 B stride) ----
    uint32_t cpaOff0; const float* cpaSrc0;
    if (PHASE == 1) {
        int m = tid >> 3, u = tid & 7;
        cpaOff0 = (uint32_t)(m * 128 + ((u ^ (m & 7)) << 4));
        cpaSrc0 = we + (size_t)(mbase + m) * H_N + kseg + u * 4;
        // per-i advance: +32 rows = 16384 floats gmem, +4096 B smem
    } else {
        int k = tid >> 5, u = tid & 31;
        cpaOff0 = (uint32_t)(k * 512 + ((u ^ (k & 7)) << 4));
        cpaSrc0 = we + (size_t)(kseg + k) * H_N + mbase + u * 4;
        // per-i advance: +8 rows = 4096 floats gmem, +4096 B smem
    }
    // B indices (phase-dependent)
    int bt0 = 0, bt1 = 0;
    uint32_t bOff[2][2];
    int n4 = 0, kp = 0; uint32_t bOff2[4];
    if (PHASE == 1) {
        #pragma unroll
        for (int i = 0; i < 2; ++i) {
            int q = tid + i * 256;
            int qq = (q < 384) ? q : 0;
            int t = qq >> 3, k4 = qq & 7;
            if (i == 0) bt0 = t; else bt1 = t;
            bOff[i][0] = bidx(t, 2 * k4);
            bOff[i][1] = bidx(t, 2 * k4 + 1);
        }
    } else {
        n4 = tid % 12; kp = tid / 12;
        #pragma unroll
        for (int j = 0; j < 4; ++j) bOff2[j] = bidx(n4 * 4 + j, kp);
    }
    const int m0 = w * 16 + g;

    float4 rB[2][2];

    for (int tbase = 0; tbase < cnt; tbase += 48) {
        const int nlim = (cnt - tbase < 48) ? (cnt - tbase) : 48;
        const int nbl  = (nlim + 7) >> 3;

        const float* b2src = (PHASE == 2)
            ? g_hbufT + (size_t)(kseg + 2 * kp) * HB_STRIDE + poff + tbase + n4 * 4
            : nullptr;

        auto cpA = [&](int slot, int c) {
            const uint32_t sb = aAddr + slot * A_SLOT_B + cpaOff0;
            const float* src = (PHASE == 1) ? cpaSrc0 + c * 32
                                            : cpaSrc0 + (size_t)(c * 32) * H_N;
            #pragma unroll
            for (int i = 0; i < 4; ++i) {
                cp16(sb + i * 4096,
                     src + (size_t)i * ((PHASE == 1) ? 16384 : 4096));
            }
        };
        auto ldB = [&](int set, int c) {
            const int k0 = c * 32;
            if (PHASE == 1) {
                if (tbase + bt0 < cnt)
                    rB[set][0] = *(const float4*)&x[(size_t)(toff + tbase + bt0) * H_N + k0 + (tid & 7) * 4];
                else
                    rB[set][0] = make_float4(0.f, 0.f, 0.f, 0.f);
                if (tid < 128) {
                    if (tbase + bt1 < cnt)
                        rB[set][1] = *(const float4*)&x[(size_t)(toff + tbase + bt1) * H_N + k0 + (tid & 7) * 4];
                    else
                        rB[set][1] = make_float4(0.f, 0.f, 0.f, 0.f);
                }
            } else {
                if (tid < 192) {
                    const float* p0 = b2src + (size_t)k0 * HB_STRIDE;
                    rB[set][0] = *(const float4*)p0;
                    rB[set][1] = *(const float4*)(p0 + HB_STRIDE);
                }
            }
        };
        auto stsB = [&](int buf, int set) {
            uint32_t* Bs = Bh + buf * BSZ_U32;
            if (PHASE == 1) {
                Bs[bOff[0][0]] = pack2(rB[set][0].x, rB[set][0].y);
                Bs[bOff[0][1]] = pack2(rB[set][0].z, rB[set][0].w);
                if (tid < 128) {
                    Bs[bOff[1][0]] = pack2(rB[set][1].x, rB[set][1].y);
                    Bs[bOff[1][1]] = pack2(rB[set][1].z, rB[set][1].w);
                }
            } else {
                if (tid < 192) {
                    const float* a = (const float*)&rB[set][0];
                    const float* b = (const float*)&rB[set][1];
                    #pragma unroll
                    for (int j = 0; j < 4; ++j)
                        Bs[bOff2[j]] = pack2(a[j], b[j]);
                }
            }
        };

        float acc[6][4];
        #pragma unroll
        for (int nb = 0; nb < 6; ++nb)
            #pragma unroll
            for (int r = 0; r < 4; ++r) acc[nb][r] = 0.f;

        // -------- prologue: 3 A slots in flight, B 2 ahead --------
        ldB(0, 0); ldB(1, 1);
        stsB(0, 0);
        ldB(0, 2);
        cpA(0, 0); cp_commit();
        cpA(1, 1); cp_commit();
        cpA(2, 2); cp_commit();
        __syncthreads();

        // -------- mainloop --------
        int sl = 0;   // c % 3
        #pragma unroll 2
        for (int c = 0; c < NCH; ++c) {
            cp_wait<2>();              // slot c's group complete
            __syncthreads();
            if (c + 1 < NCH) stsB((c + 1) & 1, (c + 1) & 1);
            if (c + 3 < NCH) ldB((c + 3) & 1, c + 3);

            const uint8_t*  As = Ab + sl * A_SLOT_B;
            const uint32_t* Bs = Bh + (c & 1) * BSZ_U32;
            #pragma unroll
            for (int kb = 0; kb < 2; ++kb) {
                const int k = 2 * tg + 16 * kb;
                uint32_t a[4];
                if (PHASE == 1) {
                    auto ld2 = [&](int m, int kk) -> float2 {
                        int off = m * 128 + (((kk >> 2) ^ (m & 7)) << 4) + ((kk & 3) << 2);
                        return *(const float2*)(As + off);
                    };
                    float2 v00 = ld2(m0, k),     v10 = ld2(m0 + 8, k);
                    float2 v01 = ld2(m0, k + 8), v11 = ld2(m0 + 8, k + 8);
                    a[0] = pack2(v00.x, v00.y);
                    a[1] = pack2(v10.x, v10.y);
                    a[2] = pack2(v01.x, v01.y);
                    a[3] = pack2(v11.x, v11.y);
                } else {
                    auto ld1 = [&](int kk, int h) -> float {
                        int off = kk * 512 + (((h >> 2) ^ (kk & 7)) << 4) + ((h & 3) << 2);
                        return *(const float*)(As + off);
                    };
                    a[0] = pack2(ld1(k, m0),     ld1(k + 1, m0));
                    a[1] = pack2(ld1(k, m0 + 8), ld1(k + 1, m0 + 8));
                    a[2] = pack2(ld1(k + 8, m0),     ld1(k + 9, m0));
                    a[3] = pack2(ld1(k + 8, m0 + 8), ld1(k + 9, m0 + 8));
                }
                #pragma unroll
                for (int nb = 0; nb < 6; ++nb) {
                    if (nb < nbl) {
                        const uint32_t* bb = &Bs[(nb * 2 + kb) * 66];
                        uint2 pb = *(const uint2*)&bb[2 * lane];
                        mma16(acc[nb], a[0], a[1], a[2], a[3], pb.x, pb.y);
                    }
                }
            }
            __syncthreads();           // all warps done with slot c
            if (c + 3 < NCH) cpA(sl, c + 3);   // refill freed slot (c%3)
            cp_commit();               // keep pending-group count at 3
            sl = (sl == 2) ? 0 : sl + 1;
        }
        cp_wait<0>();

        // -------- epilogue --------
        {
            const int r0 = mbase + m0;
            const int r1 = r0 + 8;
            float* pout = g_part + (size_t)((PHASE == 2) ? blockIdx.z : 0) * T_N * H_N;
            #pragma unroll
            for (int nb = 0; nb < 6; ++nb) {
                const int n0 = nb * 8 + tg * 2;
                const float* c4 = acc[nb];
                if (PHASE == 1) {
                    size_t b0 = (size_t)r0 * HB_STRIDE + poff + tbase + n0;
                    size_t b1 = (size_t)r1 * HB_STRIDE + poff + tbase + n0;
                    if (n0 + 1 < nlim) {
                        *(float2*)&g_hbufT[b0] = make_float2(gelu_exact(c4[0]), gelu_exact(c4[1]));
                        *(float2*)&g_hbufT[b1] = make_float2(gelu_exact(c4[2]), gelu_exact(c4[3]));
                    } else if (n0 < nlim) {
                        g_hbufT[b0] = gelu_exact(c4[0]);
                        g_hbufT[b1] = gelu_exact(c4[2]);
                    }
                } else {
                    const int t0 = toff + tbase + n0;
                    if (n0 < nlim) {
                        pout[(size_t)t0 * H_N + r0] = c4[0];
                        pout[(size_t)t0 * H_N + r1] = c4[2];
                    }
                    if (n0 + 1 < nlim) {
                        pout[(size_t)(t0 + 1) * H_N + r0] = c4[1];
                        pout[(size_t)(t0 + 1) * H_N + r1] = c4[3];
                    }
                }
            }
        }
        __syncthreads();  // smem reuse across token tiles
    }
}

// Deterministic split-K reduction: out[t,h] = sum over KSPLIT partials.
__global__ void __launch_bounds__(256)
reduce_kernel(float* __restrict__ outp) {
    const size_t i = (size_t)blockIdx.x * 256 + threadIdx.x;   // float4 index
    const size_t NV = (size_t)T_N * H_N / 4;
    if (i < NV) {
        const float4* p = (const float4*)g_part;
        float4 a = p[i];
        #pragma unroll
        for (int s = 1; s < KSPLIT; ++s) {
            float4 b = p[i + s * NV];
            a.x += b.x; a.y += b.y; a.z += b.z; a.w += b.w;
        }
        ((float4*)outp)[i] = a;
    }
}

// ---------------------------------------------------------------------------
// Inputs: d_in[0]=x [T,H] f32, d_in[1]=w1 [E,F,H] f32, d_in[2]=w2 [E,F,H] f32,
//         d_in[3]=tokens_per_expert [E] i32.  d_out=[T,H] f32.
// ---------------------------------------------------------------------------
extern "C" void kernel_launch(void* const* d_in, const int* in_sizes, int n_in,
                              void* d_out, int out_size) {
    const float* x      = (const float*)d_in[0];
    const float* w1     = (const float*)d_in[1];
    const float* w2     = (const float*)d_in[2];
    const int*   counts = (const int*)d_in[3];
    float* out = (float*)d_out;

    cudaFuncSetAttribute(mlp_kernel<1>, cudaFuncAttributeMaxDynamicSharedMemorySize, SMEM_BYTES);
    cudaFuncSetAttribute(mlp_kernel<2>, cudaFuncAttributeMaxDynamicSharedMemorySize, SMEM_BYTES);

    mlp_kernel<1><<<dim3(F_N / 128, E_N, 1), 256, SMEM_BYTES>>>(x, w1, counts);
    mlp_kernel<2><<<dim3(H_N / 128, E_N, KSPLIT), 256, SMEM_BYTES>>>(x, w2, counts);
    reduce_kernel<<<(T_N * H_N / 4 + 255) / 256, 256>>>(out);
}

// round 15
// speedup vs baseline: 1.4616x; 1.0535x over previous
#include <cuda_runtime.h>
#include <cuda_fp16.h>
#include <math.h>
#include <stdint.h>

#define E_N 64
#define H_N 512
#define F_N 2048
#define T_N 2048
#define KSPLIT 4         // phase-2 K segments
#define HB_STRIDE 3072   // padded token columns across all experts

// Scratch (device globals; zero-initialized at module load).
__device__ __half g_hbufT[(size_t)F_N * HB_STRIDE];           // 12 MB [f][tok] fp16
__device__ float  g_part[(size_t)KSPLIT * T_N * H_N];         // 16 MB [seg][t][h]

__device__ __forceinline__ float gelu_exact(float v) {
    return 0.5f * v * (1.0f + erff(v * 0.70710678118654752f));
}
// Pack two fp32 into half2: lo = a, hi = b.
__device__ __forceinline__ uint32_t pack2(float a, float b) {
    uint32_t u;
    asm("cvt.rn.f16x2.f32 %0, %1, %2;" : "=r"(u) : "f"(b), "f"(a));
    return u;
}
__device__ __forceinline__ void mma16(float c[4], uint32_t a0, uint32_t a1,
                                      uint32_t a2, uint32_t a3,
                                      uint32_t b0, uint32_t b1) {
    asm volatile(
        "mma.sync.aligned.m16n8k16.row.col.f32.f16.f16.f32 "
        "{%0,%1,%2,%3},{%4,%5,%6,%7},{%8,%9},{%0,%1,%2,%3};"
        : "+f"(c[0]), "+f"(c[1]), "+f"(c[2]), "+f"(c[3])
        : "r"(a0), "r"(a1), "r"(a2), "r"(a3), "r"(b0), "r"(b1));
}
__device__ __forceinline__ void cp16(uint32_t dst, const void* src) {
    asm volatile("cp.async.cg.shared.global [%0], [%1], 16;"
                 :: "r"(dst), "l"(src) : "memory");
}
__device__ __forceinline__ void cp_commit() {
    asm volatile("cp.async.commit_group;" ::: "memory");
}
template <int N>
__device__ __forceinline__ void cp_wait() {
    asm volatile("cp.async.wait_group %0;" :: "n"(N) : "memory");
}
// fp16 fragment-pair B layout index (u32 units).
__device__ __forceinline__ uint32_t bidx(int n, int p) {
    int pb = p & 7;
    return ((n >> 3) * 2 + (p >> 3)) * 66 + (n & 7) * 8 + (pb & 3) * 2 + (pb >> 2);
}

// ---------------------------------------------------------------------------
// 256 threads, 4 CTAs/SM, BM=128 (one m-block per warp), BN=48, BK=32.
// A (weights): fp32 via cp.async, 3 slots of 16 KB, XOR-swizzled.
// B: fp16 fragment-pair layout, 2 buffers, reg-staged 2 chunks ahead.
//   phase1 source: x (fp32, cvt on STS); phase2 source: fp16 hbuf (PRMT on STS).
// Per chunk: wait<2>; bar; stsB(c+1); ldB(c+3); MMA(c); bar; cpA(c+3); commit.
// All A-fragment smem offsets precomputed (loop-invariant).
// PHASE 2 split-K: blockIdx.z = 512-k segment; partials -> g_part[seg].
// ---------------------------------------------------------------------------
#define A_SLOT_B 16384
#define BSZ_U32 (6 * 2 * 66)
#define SMEM_BYTES (3 * A_SLOT_B + 2 * BSZ_U32 * 4)   // 55488 -> 4 CTAs/SM

template <int PHASE>
__global__ void __launch_bounds__(256, 4)
mlp_kernel(const float* __restrict__ x, const float* __restrict__ wgt,
           const int* __restrict__ counts) {
    constexpr int NCH = 16;   // 16 chunks of 32 k per CTA

    extern __shared__ __align__(16) uint8_t smem_raw[];
    uint8_t*  Ab  = smem_raw;                               // 3 fp32 A slots
    uint32_t* Bh  = (uint32_t*)(smem_raw + 3 * A_SLOT_B);   // 2 fp16 B bufs
    const uint32_t aAddr = (uint32_t)__cvta_generic_to_shared(Ab);

    const int tid = threadIdx.x;
    const int w = tid >> 5, lane = tid & 31;
    const int g = lane >> 2, tg = lane & 3;
    const int e = blockIdx.y;
    const int mbase = blockIdx.x * 128;
    const int kseg  = (PHASE == 2) ? blockIdx.z * 512 : 0;

    // ---- in-kernel scan of tokens_per_expert (warp 0) ----
    __shared__ int s_sc[3];
    if (tid < 32) {
        const unsigned FULL = 0xffffffffu;
        int c0 = counts[lane], c1 = counts[lane + 32];
        int p0 = (c0 + 15) & ~15, p1 = (c1 + 15) & ~15;
        int i0 = c0, i1 = c1, q0 = p0, q1 = p1;
        #pragma unroll
        for (int d = 1; d < 32; d <<= 1) {
            int t;
            t = __shfl_up_sync(FULL, i0, d); if (lane >= d) i0 += t;
            t = __shfl_up_sync(FULL, i1, d); if (lane >= d) i1 += t;
            t = __shfl_up_sync(FULL, q0, d); if (lane >= d) q0 += t;
            t = __shfl_up_sync(FULL, q1, d); if (lane >= d) q1 += t;
        }
        int tot0  = __shfl_sync(FULL, i0, 31);
        int ptot0 = __shfl_sync(FULL, q0, 31);
        int el = e & 31, ex, cc, pex;
        if (e < 32) {
            ex  = __shfl_sync(FULL, i0, el) - __shfl_sync(FULL, c0, el);
            cc  = __shfl_sync(FULL, c0, el);
            pex = __shfl_sync(FULL, q0, el) - __shfl_sync(FULL, p0, el);
        } else {
            ex  = tot0 + __shfl_sync(FULL, i1, el) - __shfl_sync(FULL, c1, el);
            cc  = __shfl_sync(FULL, c1, el);
            pex = ptot0 + __shfl_sync(FULL, q1, el) - __shfl_sync(FULL, p1, el);
        }
        if (lane == 0) { s_sc[0] = ex; s_sc[1] = cc; s_sc[2] = pex; }
    }
    __syncthreads();
    const int toff = s_sc[0], cnt = s_sc[1], poff = s_sc[2];
    const float* we = wgt + (size_t)e * F_N * H_N;

    // ---- loop-invariant loader state ----
    uint32_t cpaOff0; const float* cpaSrc0;
    if (PHASE == 1) {
        int m = tid >> 3, u = tid & 7;
        cpaOff0 = (uint32_t)(m * 128 + ((u ^ (m & 7)) << 4));
        cpaSrc0 = we + (size_t)(mbase + m) * H_N + kseg + u * 4;
    } else {
        int k = tid >> 5, u = tid & 31;
        cpaOff0 = (uint32_t)(k * 512 + ((u ^ (k & 7)) << 4));
        cpaSrc0 = we + (size_t)(kseg + k) * H_N + mbase + u * 4;
    }
    // B indices
    int bt0 = 0, bt1 = 0;
    uint32_t bOff[2][2];
    int n4 = 0, kp = 0; uint32_t bOff2[4];
    if (PHASE == 1) {
        #pragma unroll
        for (int i = 0; i < 2; ++i) {
            int q = tid + i * 256;
            int qq = (q < 384) ? q : 0;
            int t = qq >> 3, k4 = qq & 7;
            if (i == 0) bt0 = t; else bt1 = t;
            bOff[i][0] = bidx(t, 2 * k4);
            bOff[i][1] = bidx(t, 2 * k4 + 1);
        }
    } else {
        n4 = tid % 12; kp = tid / 12;
        #pragma unroll
        for (int j = 0; j < 4; ++j) bOff2[j] = bidx(n4 * 4 + j, kp);
    }
    const int m0 = w * 16 + g;

    // ---- precomputed A-fragment smem offsets ----
    uint32_t aOff[8];
    if (PHASE == 1) {
        #pragma unroll
        for (int kb = 0; kb < 2; ++kb) {
            const int k = 2 * tg + 16 * kb;
            aOff[kb * 4 + 0] = m0 * 128       + (((k >> 2) ^ (m0 & 7)) << 4)             + ((k & 3) << 2);
            aOff[kb * 4 + 1] = (m0 + 8) * 128 + (((k >> 2) ^ ((m0 + 8) & 7)) << 4)       + ((k & 3) << 2);
            aOff[kb * 4 + 2] = m0 * 128       + ((((k + 8) >> 2) ^ (m0 & 7)) << 4)       + (((k + 8) & 3) << 2);
            aOff[kb * 4 + 3] = (m0 + 8) * 128 + ((((k + 8) >> 2) ^ ((m0 + 8) & 7)) << 4) + (((k + 8) & 3) << 2);
        }
    } else {
        const int k = 2 * tg;   // kb = 0; kb = 1 adds 8192 ((k+16)&7 == k&7)
        auto o = [&](int kk, int h) {
            return (uint32_t)(kk * 512 + (((h >> 2) ^ (kk & 7)) << 4) + ((h & 3) << 2));
        };
        aOff[0] = o(k, m0);     aOff[1] = o(k + 1, m0);
        aOff[2] = o(k, m0 + 8); aOff[3] = o(k + 1, m0 + 8);
        aOff[4] = o(k + 8, m0);     aOff[5] = o(k + 9, m0);
        aOff[6] = o(k + 8, m0 + 8); aOff[7] = o(k + 9, m0 + 8);
    }

    float4 rB1[2][2];   // phase1 staging (fp32 x)
    uint2  rB2[2][2];   // phase2 staging (fp16 hbuf rows f, f+1)

    for (int tbase = 0; tbase < cnt; tbase += 48) {
        const int nlim = (cnt - tbase < 48) ? (cnt - tbase) : 48;
        const int nbl  = (nlim + 7) >> 3;

        const __half* b2src = (PHASE == 2)
            ? g_hbufT + (size_t)(kseg + 2 * kp) * HB_STRIDE + poff + tbase + n4 * 4
            : nullptr;

        auto cpA = [&](int slot, int c) {
            const uint32_t sb = aAddr + slot * A_SLOT_B + cpaOff0;
            const float* src = (PHASE == 1) ? cpaSrc0 + c * 32
                                            : cpaSrc0 + (size_t)(c * 32) * H_N;
            #pragma unroll
            for (int i = 0; i < 4; ++i) {
                cp16(sb + i * 4096,
                     src + (size_t)i * ((PHASE == 1) ? 16384 : 4096));
            }
        };
        auto ldB = [&](int set, int c) {
            const int k0 = c * 32;
            if (PHASE == 1) {
                if (tbase + bt0 < cnt)
                    rB1[set][0] = *(const float4*)&x[(size_t)(toff + tbase + bt0) * H_N + k0 + (tid & 7) * 4];
                else
                    rB1[set][0] = make_float4(0.f, 0.f, 0.f, 0.f);
                if (tid < 128) {
                    if (tbase + bt1 < cnt)
                        rB1[set][1] = *(const float4*)&x[(size_t)(toff + tbase + bt1) * H_N + k0 + (tid & 7) * 4];
                    else
                        rB1[set][1] = make_float4(0.f, 0.f, 0.f, 0.f);
                }
            } else {
                if (tid < 192) {
                    const __half* p0 = b2src + (size_t)k0 * HB_STRIDE;
                    rB2[set][0] = *(const uint2*)p0;                 // row f  : 4 halfs
                    rB2[set][1] = *(const uint2*)(p0 + HB_STRIDE);   // row f+1: 4 halfs
                }
            }
        };
        auto stsB = [&](int buf, int set) {
            uint32_t* Bs = Bh + buf * BSZ_U32;
            if (PHASE == 1) {
                Bs[bOff[0][0]] = pack2(rB1[set][0].x, rB1[set][0].y);
                Bs[bOff[0][1]] = pack2(rB1[set][0].z, rB1[set][0].w);
                if (tid < 128) {
                    Bs[bOff[1][0]] = pack2(rB1[set][1].x, rB1[set][1].y);
                    Bs[bOff[1][1]] = pack2(rB1[set][1].z, rB1[set][1].w);
                }
            } else {
                if (tid < 192) {
                    uint2 a = rB2[set][0], b = rB2[set][1];
                    Bs[bOff2[0]] = __byte_perm(a.x, b.x, 0x5410);  // token n4*4+0
                    Bs[bOff2[1]] = __byte_perm(a.x, b.x, 0x7632);  // +1
                    Bs[bOff2[2]] = __byte_perm(a.y, b.y, 0x5410);  // +2
                    Bs[bOff2[3]] = __byte_perm(a.y, b.y, 0x7632);  // +3
                }
            }
        };

        float acc[6][4];
        #pragma unroll
        for (int nb = 0; nb < 6; ++nb)
            #pragma unroll
            for (int r = 0; r < 4; ++r) acc[nb][r] = 0.f;

        // -------- prologue: 3 A slots in flight, B 2 ahead --------
        ldB(0, 0); ldB(1, 1);
        stsB(0, 0);
        ldB(0, 2);
        cpA(0, 0); cp_commit();
        cpA(1, 1); cp_commit();
        cpA(2, 2); cp_commit();
        __syncthreads();

        // -------- mainloop --------
        int sl = 0;   // c % 3
        #pragma unroll 2
        for (int c = 0; c < NCH; ++c) {
            cp_wait<2>();              // slot c's group complete
            __syncthreads();
            if (c + 1 < NCH) stsB((c + 1) & 1, (c + 1) & 1);
            if (c + 3 < NCH) ldB((c + 3) & 1, c + 3);

            const uint8_t*  As = Ab + sl * A_SLOT_B;
            const uint32_t* Bs = Bh + (c & 1) * BSZ_U32;
            #pragma unroll
            for (int kb = 0; kb < 2; ++kb) {
                uint32_t a[4];
                if (PHASE == 1) {
                    float2 v00 = *(const float2*)(As + aOff[kb * 4 + 0]);
                    float2 v10 = *(const float2*)(As + aOff[kb * 4 + 1]);
                    float2 v01 = *(const float2*)(As + aOff[kb * 4 + 2]);
                    float2 v11 = *(const float2*)(As + aOff[kb * 4 + 3]);
                    a[0] = pack2(v00.x, v00.y);
                    a[1] = pack2(v10.x, v10.y);
                    a[2] = pack2(v01.x, v01.y);
                    a[3] = pack2(v11.x, v11.y);
                } else {
                    const uint32_t kbAdd = kb * 8192;
                    a[0] = pack2(*(const float*)(As + aOff[0] + kbAdd),
                                 *(const float*)(As + aOff[1] + kbAdd));
                    a[1] = pack2(*(const float*)(As + aOff[2] + kbAdd),
                                 *(const float*)(As + aOff[3] + kbAdd));
                    a[2] = pack2(*(const float*)(As + aOff[4] + kbAdd),
                                 *(const float*)(As + aOff[5] + kbAdd));
                    a[3] = pack2(*(const float*)(As + aOff[6] + kbAdd),
                                 *(const float*)(As + aOff[7] + kbAdd));
                }
                #pragma unroll
                for (int nb = 0; nb < 6; ++nb) {
                    if (nb < nbl) {
                        const uint32_t* bb = &Bs[(nb * 2 + kb) * 66];
                        uint2 pb = *(const uint2*)&bb[2 * lane];
                        mma16(acc[nb], a[0], a[1], a[2], a[3], pb.x, pb.y);
                    }
                }
            }
            __syncthreads();           // all warps done with slot c
            if (c + 3 < NCH) cpA(sl, c + 3);   // refill freed slot (c%3)
            cp_commit();               // keep pending-group count at 3
            sl = (sl == 2) ? 0 : sl + 1;
        }
        cp_wait<0>();

        // -------- epilogue --------
        {
            const int r0 = mbase + m0;
            const int r1 = r0 + 8;
            float* pout = g_part + (size_t)((PHASE == 2) ? blockIdx.z : 0) * T_N * H_N;
            #pragma unroll
            for (int nb = 0; nb < 6; ++nb) {
                const int n0 = nb * 8 + tg * 2;
                const float* c4 = acc[nb];
                if (PHASE == 1) {
                    size_t b0 = (size_t)r0 * HB_STRIDE + poff + tbase + n0;
                    size_t b1 = (size_t)r1 * HB_STRIDE + poff + tbase + n0;
                    if (n0 + 1 < nlim) {
                        *(uint32_t*)&g_hbufT[b0] = pack2(gelu_exact(c4[0]), gelu_exact(c4[1]));
                        *(uint32_t*)&g_hbufT[b1] = pack2(gelu_exact(c4[2]), gelu_exact(c4[3]));
                    } else if (n0 < nlim) {
                        g_hbufT[b0] = __float2half(gelu_exact(c4[0]));
                        g_hbufT[b1] = __float2half(gelu_exact(c4[2]));
                    }
                } else {
                    const int t0 = toff + tbase + n0;
                    if (n0 < nlim) {
                        pout[(size_t)t0 * H_N + r0] = c4[0];
                        pout[(size_t)t0 * H_N + r1] = c4[2];
                    }
                    if (n0 + 1 < nlim) {
                        pout[(size_t)(t0 + 1) * H_N + r0] = c4[1];
                        pout[(size_t)(t0 + 1) * H_N + r1] = c4[3];
                    }
                }
            }
        }
        __syncthreads();  // smem reuse across token tiles
    }
}

// Deterministic split-K reduction: out[t,h] = sum over KSPLIT partials.
__global__ void __launch_bounds__(256)
reduce_kernel(float* __restrict__ outp) {
    const size_t i = (size_t)blockIdx.x * 256 + threadIdx.x;   // float4 index
    const size_t NV = (size_t)T_N * H_N / 4;
    if (i < NV) {
        const float4* p = (const float4*)g_part;
        float4 a = p[i];
        #pragma unroll
        for (int s = 1; s < KSPLIT; ++s) {
            float4 b = p[i + s * NV];
            a.x += b.x; a.y += b.y; a.z += b.z; a.w += b.w;
        }
        ((float4*)outp)[i] = a;
    }
}

// ---------------------------------------------------------------------------
// Inputs: d_in[0]=x [T,H] f32, d_in[1]=w1 [E,F,H] f32, d_in[2]=w2 [E,F,H] f32,
//         d_in[3]=tokens_per_expert [E] i32.  d_out=[T,H] f32.
// ---------------------------------------------------------------------------
extern "C" void kernel_launch(void* const* d_in, const int* in_sizes, int n_in,
                              void* d_out, int out_size) {
    const float* x      = (const float*)d_in[0];
    const float* w1     = (const float*)d_in[1];
    const float* w2     = (const float*)d_in[2];
    const int*   counts = (const int*)d_in[3];
    float* out = (float*)d_out;

    cudaFuncSetAttribute(mlp_kernel<1>, cudaFuncAttributeMaxDynamicSharedMemorySize, SMEM_BYTES);
    cudaFuncSetAttribute(mlp_kernel<2>, cudaFuncAttributeMaxDynamicSharedMemorySize, SMEM_BYTES);

    mlp_kernel<1><<<dim3(F_N / 128, E_N, 1), 256, SMEM_BYTES>>>(x, w1, counts);
    mlp_kernel<2><<<dim3(H_N / 128, E_N, KSPLIT), 256, SMEM_BYTES>>>(x, w2, counts);
    reduce_kernel<<<(T_N * H_N / 4 + 255) / 256, 256>>>(out);
}